// round 16
// baseline (speedup 1.0000x reference)
#include <cuda_runtime.h>
#include <cuda_bf16.h>
#include <cub/block/block_radix_sort.cuh>

// ---------------- problem constants ----------------
#define BB 4
#define AA 10
#define LL 4096
#define NPROP (LL * AA)          // 40960 per batch (fits in 16 bits)
#define TOTAL (BB * NPROP)       // 163840
#define PRE_NMS 6000
#define POST_NMS 300
#define NCHUNK64 ((PRE_NMS + 63) / 64)   // 94
#define NMS_THRESH_F 0.7f
#define MIN_SIZE_F 8.0f
#define FEAT_STRIDE 8
#define CLIP_MAX 32767.0f        // L*FEAT_STRIDE - 1
#define FULLMASK 0xFFFFFFFFu

#define MEGA_THREADS 1024
#define MEGA_WARPS 32
#define NHBINS 8192              // 13-bit histogram
#define ITEMS 7                  // keys per thread for block radix sort
#define SEL_CAP (MEGA_THREADS * ITEMS)   // 7168 selected-candidate capacity

using BlockRadixSortT = cub::BlockRadixSort<unsigned long long, MEGA_THREADS, ITEMS>;

static constexpr size_t SORT_REGION =
    (sizeof(typename BlockRadixSortT::TempStorage) > (size_t)SEL_CAP * 8)
        ? ((sizeof(typename BlockRadixSortT::TempStorage) + 15) & ~(size_t)15)
        : (size_t)SEL_CAP * 8;

// ---------------- static device scratch (no allocations allowed) ----------------
__device__ float2   g_box[TOTAL];   // decoded boxes, reference index order
__device__ unsigned g_dkey[TOTAL];  // descending-orderable score key (small = high score)

__constant__ float c_scales[AA] = {2.f, 4.f, 5.f, 6.f, 8.f, 9.f, 10.f, 12.f, 14.f, 16.f};

// ---------------- kernel 1: decode proposals + score keys (coalesced loads) ----------
__global__ void compute_props(const float* __restrict__ scores_in,
                              const float* __restrict__ deltas_in) {
    int t = blockIdx.x * blockDim.x + threadIdx.x;
    if (t >= TOTAL) return;
    int l = t & (LL - 1);
    int ba = t >> 12;                  // b*AA + a
    int b = ba / AA;
    int a = ba - b * AA;

    const int base = b * (2 * AA) * LL;
    float score = scores_in[base + (AA + a) * LL + l];
    float d0    = deltas_in[base + (2 * a) * LL + l];
    float d1    = deltas_in[base + (2 * a + 1) * LL + l];

    float ws   = c_scales[a] * (float)FEAT_STRIDE;
    float ctrA = ((float)FEAT_STRIDE - 1.0f) * 0.5f;      // 3.5
    float shift = (float)(l * FEAT_STRIDE);
    float x1a = ctrA - 0.5f * (ws - 1.0f) + shift;
    float x2a = ctrA + 0.5f * (ws - 1.0f) + shift;

    float width = x2a - x1a + 1.0f;
    float ctr   = x1a + 0.5f * width;

    float pred_ctr = d0 * width + ctr;
    float pred_l   = expf(d1) * width;

    float x1 = pred_ctr - 0.5f * pred_l;
    float x2 = pred_ctr + 0.5f * pred_l;
    x1 = fminf(fmaxf(x1, 0.0f), CLIP_MAX);
    x2 = fminf(fmaxf(x2, 0.0f), CLIP_MAX);

    float ls = x2 - x1 + 1.0f;
    if (ls < MIN_SIZE_F) score = 0.0f;

    int r = l * AA + a;                // reference proposal index within batch
    int idx = b * NPROP + r;
    g_box[idx] = make_float2(x1, x2);

    // ascending-orderable then invert: small dkey = high score
    unsigned u = __float_as_uint(score);
    unsigned asc = (u & 0x80000000u) ? ~u : (u | 0x80000000u);
    g_dkey[idx] = ~asc;
}

__device__ __forceinline__ bool iou_gt(float ax1, float ax2, float alen,
                                       float bx1, float bx2, float blen) {
    float inter = fminf(ax2, bx2) - fmaxf(ax1, bx1) + 1.0f;
    float uni = alen + blen - inter;
    if (inter > 0.6999f * uni) {
        if (inter / uni > NMS_THRESH_F) return true;   // decision by division
    }
    return false;
}

// ---------------- kernel 2: mega — select + block radix sort + 64-wide greedy NMS ----
__global__ void __launch_bounds__(MEGA_THREADS)
mega_kernel(float* __restrict__ out) {
    extern __shared__ unsigned char raw[];
    unsigned long long* s_sort = (unsigned long long*)raw;        // extraction buffer
    float2* sboxes = (float2*)(raw + SORT_REGION);
    float4* skept  = (float4*)(sboxes + PRE_NMS);
    __shared__ unsigned s_hist[NHBINS];          // 32 KB
    __shared__ unsigned s_wsum[MEGA_WARPS];
    __shared__ unsigned s_sup0[MEGA_WARPS];
    __shared__ unsigned s_sup1[MEGA_WARPS];
    __shared__ unsigned long long s_frow[64];    // finished 64-bit suppression rows
    __shared__ unsigned s_T, s_B0, s_cnt;
    __shared__ int s_K;

    const int b    = blockIdx.x;
    const int tid  = threadIdx.x;
    const int wid  = tid >> 5;
    const int lane = tid & 31;

    for (int i = tid; i < NHBINS; i += MEGA_THREADS) s_hist[i] = 0;
    for (int i = tid; i < POST_NMS; i += MEGA_THREADS) {
        float* o = out + (b * POST_NMS + i) * 3;
        o[0] = (float)b; o[1] = 0.0f; o[2] = 0.0f;
    }
    if (tid == 0) { s_cnt = 0; s_K = 0; }
    __syncthreads();

    const unsigned* __restrict__ dk = g_dkey + b * NPROP;

    // ---- histogram of top 13 key bits (uint4 loads) ----
    {
        const uint4* dk4 = (const uint4*)dk;
        for (int i = tid; i < NPROP / 4; i += MEGA_THREADS) {
            uint4 v = dk4[i];
            atomicAdd(&s_hist[v.x >> 19], 1u);
            atomicAdd(&s_hist[v.y >> 19], 1u);
            atomicAdd(&s_hist[v.z >> 19], 1u);
            atomicAdd(&s_hist[v.w >> 19], 1u);
        }
    }
    __syncthreads();

    // ---- scan (shfl 3-level): find threshold bin T and first nonempty bin B0 ----
    {
        const int base = tid * (NHBINS / MEGA_THREADS);   // 8 bins per thread
        unsigned own = 0;
        #pragma unroll
        for (int k = 0; k < NHBINS / MEGA_THREADS; ++k) own += s_hist[base + k];
        unsigned inc = own;
        #pragma unroll
        for (int off = 1; off < 32; off <<= 1) {
            unsigned v = __shfl_up_sync(FULLMASK, inc, off);
            if (lane >= off) inc += v;
        }
        if (lane == 31) s_wsum[wid] = inc;
        __syncthreads();
        if (wid == 0) {
            unsigned w = s_wsum[lane];
            #pragma unroll
            for (int off = 1; off < 32; off <<= 1) {
                unsigned v = __shfl_up_sync(FULLMASK, w, off);
                if (lane >= off) w += v;
            }
            s_wsum[lane] = w - s_wsum[lane];   // exclusive warp prefix
        }
        __syncthreads();
        unsigned before = s_wsum[wid] + (inc - own);   // global exclusive prefix
        unsigned incl = before + own;
        if (before < PRE_NMS && incl >= PRE_NMS) {     // threshold crossing
            unsigned cum = before;
            #pragma unroll
            for (int k = 0; k < NHBINS / MEGA_THREADS; ++k) {
                cum += s_hist[base + k];
                if (cum >= PRE_NMS) { s_T = (unsigned)(base + k); break; }
            }
        }
        if (before == 0 && own > 0) {                  // first nonempty bin
            #pragma unroll
            for (int k = 0; k < NHBINS / MEGA_THREADS; ++k) {
                if (s_hist[base + k] > 0) { s_B0 = (unsigned)(base + k); break; }
            }
        }
        __syncthreads();
    }
    const unsigned T  = s_T;
    const unsigned B0 = s_B0;
    const unsigned dbase = B0 << 19;

    int end_bit;
    {
        unsigned span_bins = T + 1 - B0;
        int dbits = (span_bins <= 1) ? 19 : (19 + (32 - __clz(span_bins - 1)));
        end_bit = 16 + dbits;
        if (end_bit > 48) end_bit = 48;
    }

    // ---- extract selected candidates (warp-aggregated, rebased 48-bit keys) ----
    for (int i = tid; i < NPROP; i += MEGA_THREADS) {
        unsigned d = dk[i];
        bool p = ((d >> 19) <= T);
        unsigned mask = __ballot_sync(FULLMASK, p);
        if (mask) {
            int leader = __ffs(mask) - 1;
            unsigned wbase = 0;
            if (lane == leader) wbase = atomicAdd(&s_cnt, (unsigned)__popc(mask));
            wbase = __shfl_sync(FULLMASK, wbase, leader);
            if (p) {
                unsigned slot = wbase + __popc(mask & ((1u << lane) - 1u));
                if (slot < SEL_CAP)
                    s_sort[slot] = ((unsigned long long)(d - dbase) << 16) | (unsigned)i;
            }
        }
    }
    __syncthreads();
    const unsigned C = s_cnt;
    for (int i = tid; i < SEL_CAP; i += MEGA_THREADS)
        if ((unsigned)i >= C) s_sort[i] = ~0ULL;
    __syncthreads();

    // ---- block radix sort (keys in registers; smem region reused as temp storage) ----
    {
        unsigned long long keys[ITEMS];
        #pragma unroll
        for (int k = 0; k < ITEMS; ++k) keys[k] = s_sort[tid * ITEMS + k];
        __syncthreads();   // extraction buffer dead; safe to alias as temp storage

        BlockRadixSortT(*reinterpret_cast<typename BlockRadixSortT::TempStorage*>(raw))
            .Sort(keys, 0, end_bit);
        __syncthreads();

        #pragma unroll
        for (int k = 0; k < ITEMS; ++k) {
            int rank = tid * ITEMS + k;
            if (rank < PRE_NMS) {
                int r = (int)(keys[k] & 0xFFFFu);
                sboxes[rank] = g_box[b * NPROP + r];
            }
        }
    }
    __syncthreads();

    // ---- 64-wide chunked greedy NMS ----
    for (int c = 0; c < NCHUNK64; ++c) {
        const int cb = c * 64;
        const int nvalid = PRE_NMS - cb;          // >= 48 always (6000 = 93*64+48)
        const unsigned vm0 = (nvalid >= 32) ? FULLMASK : ((1u << nvalid) - 1u);
        const unsigned vm1 = (nvalid >= 64) ? FULLMASK
                            : (nvalid > 32 ? ((1u << (nvalid - 32)) - 1u) : 0u);
        const unsigned long long vm64 =
            (unsigned long long)vm0 | ((unsigned long long)vm1 << 32);

        const int i0 = cb + lane;
        const int i1 = cb + 32 + lane;
        const bool v0 = (i0 < PRE_NMS);
        const bool v1 = (i1 < PRE_NMS);

        float ax1 = 0.0f, ax2 = -2.0f, bx1 = 0.0f, bx2 = -2.0f;
        if (v0) { float2 t0 = sboxes[i0]; ax1 = t0.x; ax2 = t0.y; }
        if (v1) { float2 t1 = sboxes[i1]; bx1 = t1.x; bx2 = t1.y; }
        const float alen = ax2 - ax1 + 1.0f;
        const float blen = bx2 - bx1 + 1.0f;
        const int K = s_K;

        // ---- phase 1 (all 32 warps): both candidates vs kept list ----
        bool sup0 = !v0, sup1 = !v1;
        int it = 0;
        for (int j = wid; j < K; j += MEGA_WARPS) {
            float4 kb = skept[j];                    // broadcast within warp
            if (!sup0 && iou_gt(ax1, ax2, alen, kb.x, kb.y, kb.z)) sup0 = true;
            if (!sup1 && iou_gt(bx1, bx2, blen, kb.x, kb.y, kb.z)) sup1 = true;
            if (((++it) & 3) == 0 && __all_sync(FULLMASK, sup0 && sup1)) break;
        }
        {
            unsigned b0 = __ballot_sync(FULLMASK, sup0);
            unsigned b1 = __ballot_sync(FULLMASK, sup1);
            if (lane == 0) { s_sup0[wid] = b0; s_sup1[wid] = b1; }
        }

        // ---- phase 2: warp w builds FULL rows for candidates cb+w and cb+32+w ----
        {
            float2 p0 = make_float2(0.0f, -2.0f);
            float2 p1 = make_float2(0.0f, -2.0f);
            if (cb + wid < PRE_NMS)      p0 = sboxes[cb + wid];        // broadcast
            if (cb + 32 + wid < PRE_NMS) p1 = sboxes[cb + 32 + wid];   // broadcast
            float p0len = p0.y - p0.x + 1.0f;
            float p1len = p1.y - p1.x + 1.0f;

            bool o00 = iou_gt(p0.x, p0.y, p0len, ax1, ax2, alen);
            bool o01 = iou_gt(p0.x, p0.y, p0len, bx1, bx2, blen);
            bool o10 = iou_gt(p1.x, p1.y, p1len, ax1, ax2, alen);
            bool o11 = iou_gt(p1.x, p1.y, p1len, bx1, bx2, blen);

            unsigned long long row0 =
                ((unsigned long long)__ballot_sync(FULLMASK, o00)) |
                ((unsigned long long)__ballot_sync(FULLMASK, o01) << 32);
            unsigned long long row1 =
                ((unsigned long long)__ballot_sync(FULLMASK, o10)) |
                ((unsigned long long)__ballot_sync(FULLMASK, o11) << 32);
            row0 = (row0 & vm64) & ~(1ULL << wid);          // clear self bit
            row1 = (row1 & vm64) & ~(1ULL << (32 + wid));   // clear self bit
            if (lane == 0) { s_frow[wid] = row0; s_frow[32 + wid] = row1; }
        }
        __syncthreads();

        // ---- phases 3-4 (warp 0): 64-bit resolve + append ----
        if (wid == 0) {
            unsigned or0 = __reduce_or_sync(FULLMASK, s_sup0[lane]);
            unsigned or1 = __reduce_or_sync(FULLMASK, s_sup1[lane]);
            unsigned long long removed =
                ((unsigned long long)(or0 | ~vm0)) |
                ((unsigned long long)(or1 | ~vm1) << 32);

            unsigned long long keptbits = 0ULL;
            unsigned long long alive = ~removed;
            while (alive) {
                int p = __ffsll(alive) - 1;                  // uniform
                keptbits |= 1ULL << p;
                removed |= s_frow[p];                        // broadcast LDS
                alive = ~removed & ~((2ULL << p) - 1ULL);
            }

            int nk = __popcll(keptbits);
            if (nk) {
                if ((keptbits >> lane) & 1ULL) {
                    int rank = K + __popcll(keptbits & ((1ULL << lane) - 1ULL));
                    if (rank < POST_NMS) {
                        skept[rank] = make_float4(ax1, ax2, alen, 0.0f);
                        float* o = out + (b * POST_NMS + rank) * 3;
                        o[1] = ax1; o[2] = ax2;
                    }
                }
                if ((keptbits >> (32 + lane)) & 1ULL) {
                    int rank = K + __popcll(keptbits & ((1ULL << (32 + lane)) - 1ULL));
                    if (rank < POST_NMS) {
                        skept[rank] = make_float4(bx1, bx2, blen, 0.0f);
                        float* o = out + (b * POST_NMS + rank) * 3;
                        o[1] = bx1; o[2] = bx2;
                    }
                }
                if (lane == 0) s_K = K + nk;
            }
        }
        __syncthreads();
        if (s_K >= POST_NMS) break;
    }
}

// ---------------- host launcher ----------------
extern "C" void kernel_launch(void* const* d_in, const int* in_sizes, int n_in,
                              void* d_out, int out_size) {
    (void)in_sizes; (void)n_in; (void)out_size;
    const float* scores = (const float*)d_in[0];
    const float* deltas = (const float*)d_in[1];
    float* out = (float*)d_out;

    compute_props<<<(TOTAL + 255) / 256, 256>>>(scores, deltas);

    const int smem_bytes = (int)SORT_REGION
                         + PRE_NMS * (int)sizeof(float2)
                         + POST_NMS * (int)sizeof(float4);
    cudaFuncSetAttribute(mega_kernel, cudaFuncAttributeMaxDynamicSharedMemorySize, smem_bytes);
    mega_kernel<<<BB, MEGA_THREADS, smem_bytes>>>(out);
}